// round 1
// baseline (speedup 1.0000x reference)
#include <cuda_runtime.h>

// LocalNorm2d: 32x32 box-filter local normalization, reflect padding.
// x: (32,3,512,512) fp32 -> out same shape.
//
// Fused single kernel:
//   - block = one (n,c) image x one 128-row segment, full 544-wide padded row
//   - 136 active threads own 4 padded columns each; running vertical sums
//     (colsum / colsumsq) in registers, 32-row x ring in smem
//   - horizontal 32-window via exclusive prefix E: W[o] = E[o+32] - E[o],
//     prefix built from 3 local adds + 5-step warp shfl scan + cross-warp fixup

namespace {
constexpr int Hh   = 512;
constexpr int Ww   = 512;
constexpr int KSZ  = 32;
constexpr int PDv  = 16;
constexpr int PADW = 544;   // Ww + 2*PDv
constexpr int NT   = 160;   // threads per block (5 warps)
constexpr int NACT = 136;   // PADW / 4 column-owning threads
constexpr int RSEG = 128;   // output rows per block
constexpr int NIMG = 32 * 3;
constexpr int SMEM_FLOATS = KSZ * PADW + 2 * PADW + 16;
constexpr int SMEM_BYTES  = SMEM_FLOATS * 4;  // 74048 B
}

__device__ __forceinline__ float norm1(float wsum, float wsq, float xc) {
    const float inv = 1.0f / 1024.0f;   // 1/(KS*KS)
    float mean = wsum * inv;
    float msq  = wsq * inv;
    float var  = fabsf(fmaf(-mean, mean, msq));
    float rs   = __frsqrt_rn(fmaxf(var, 1e-24f));
    float stdv = var * rs;              // sqrt(var), approx (rel err ~2^-22)
    float v    = __fdividef(xc - mean, stdv + 1e-10f);
    return fminf(6.0f, fmaxf(-6.0f, v));
}

__global__ __launch_bounds__(NT, 3)
void localnorm_kernel(const float* __restrict__ x, float* __restrict__ out)
{
    extern __shared__ float smem[];
    float* ring = smem;                       // [KSZ][PADW]
    float* Es   = smem + KSZ * PADW;          // [PADW] exclusive prefix of colsum
    float* Eq   = Es + PADW;                  // [PADW] exclusive prefix of colsumsq
    float* wts  = Eq + PADW;                  // [8] warp totals
    float* wtq  = wts + 8;

    const int t      = threadIdx.x;
    const int img    = blockIdx.y;            // 0..95
    const int rstart = blockIdx.x * RSEG;     // output row base
    const float* __restrict__ xin = x + (size_t)img * (Hh * Ww);
    float* __restrict__ op        = out + (size_t)img * (Hh * Ww);

    // zero the ring (first 32 iterations then subtract 0)
    {
        float4 z = make_float4(0.f, 0.f, 0.f, 0.f);
        float4* r4 = reinterpret_cast<float4*>(ring);
        #pragma unroll 4
        for (int i = t; i < KSZ * PADW / 4; i += NT) r4[i] = z;
    }
    __syncthreads();

    const int  c0       = 4 * t;              // padded column base
    const bool active   = (t < NACT);
    const bool interior = (t >= 4 && t <= 131);  // all 4 cols map contiguously
    int cm0 = 0, cm1 = 0, cm2 = 0, cm3 = 0;
    if (active) {
        auto rmap = [](int q) {
            q = q < 0 ? -q : q;
            return q > (Ww - 1) ? 2 * (Ww - 1) - q : q;
        };
        cm0 = rmap(c0 + 0 - PDv);
        cm1 = rmap(c0 + 1 - PDv);
        cm2 = rmap(c0 + 2 - PDv);
        cm3 = rmap(c0 + 3 - PDv);
    }

    float s0 = 0.f, s1 = 0.f, s2 = 0.f, s3 = 0.f;   // column sums
    float q0 = 0.f, q1 = 0.f, q2 = 0.f, q3 = 0.f;   // column sums of squares
    const int lane = t & 31;
    const int wrp  = t >> 5;

    for (int p = rstart; p < rstart + RSEG + KSZ - 1; ++p) {
        // padded row p -> original row (reflect)
        int rq = p - PDv;
        rq = rq < 0 ? -rq : rq;
        rq = rq > (Hh - 1) ? 2 * (Hh - 1) - rq : rq;
        const float* rowp = xin + rq * Ww;

        if (active) {
            float4 xn;
            if (interior) {
                xn = *reinterpret_cast<const float4*>(rowp + (c0 - PDv));
            } else {
                xn.x = rowp[cm0]; xn.y = rowp[cm1];
                xn.z = rowp[cm2]; xn.w = rowp[cm3];
            }
            float4* rr = reinterpret_cast<float4*>(&ring[(p & (KSZ - 1)) * PADW + c0]);
            float4 xo = *rr;
            *rr = xn;
            s0 += xn.x - xo.x; s1 += xn.y - xo.y;
            s2 += xn.z - xo.z; s3 += xn.w - xo.w;
            q0 = fmaf(xn.x, xn.x, q0); q0 = fmaf(-xo.x, xo.x, q0);
            q1 = fmaf(xn.y, xn.y, q1); q1 = fmaf(-xo.y, xo.y, q1);
            q2 = fmaf(xn.z, xn.z, q2); q2 = fmaf(-xo.z, xo.z, q2);
            q3 = fmaf(xn.w, xn.w, q3); q3 = fmaf(-xo.w, xo.w, q3);
        }

        if (p >= rstart + KSZ - 1) {           // uniform branch -> barriers legal
            // thread-local inclusive prefixes over its 4 columns
            float i1 = s0 + s1, i2 = i1 + s2, i3 = i2 + s3;
            float j1 = q0 + q1, j2 = j1 + q2, j3 = j2 + q3;

            // warp-inclusive scan of thread totals (inactive threads carry 0)
            float ts = i3, tq = j3;
            #pragma unroll
            for (int off = 1; off < 32; off <<= 1) {
                float us = __shfl_up_sync(0xFFFFFFFFu, ts, off);
                float uq = __shfl_up_sync(0xFFFFFFFFu, tq, off);
                if (lane >= off) { ts += us; tq += uq; }
            }
            if (lane == 31) { wts[wrp] = ts; wtq[wrp] = tq; }
            __syncthreads();

            float offs = 0.f, offq = 0.f;
            if (wrp > 0) { offs += wts[0]; offq += wtq[0]; }
            if (wrp > 1) { offs += wts[1]; offq += wtq[1]; }
            if (wrp > 2) { offs += wts[2]; offq += wtq[2]; }
            if (wrp > 3) { offs += wts[3]; offq += wtq[3]; }

            if (active) {
                float bs = offs + (ts - i3);   // E[4t] (exclusive)
                float bq = offq + (tq - j3);
                float4 es = make_float4(bs, bs + s0, bs + i1, bs + i2);
                float4 eq = make_float4(bq, bq + q0, bq + j1, bq + j2);
                reinterpret_cast<float4*>(Es)[t] = es;
                reinterpret_cast<float4*>(Eq)[t] = eq;
            }
            __syncthreads();

            if (t < 128) {
                const int i = p - (KSZ - 1);   // output row
                float4 el = reinterpret_cast<float4*>(Es)[t];
                float4 eh = reinterpret_cast<float4*>(Es)[t + 8];
                float4 ql = reinterpret_cast<float4*>(Eq)[t];
                float4 qh = reinterpret_cast<float4*>(Eq)[t + 8];
                // center x(i, 4t..4t+3) lives in ring row (i+16), cols c0+16..
                float4 xc = *reinterpret_cast<float4*>(
                    &ring[((i + PDv) & (KSZ - 1)) * PADW + c0 + PDv]);
                float4 r;
                r.x = norm1(eh.x - el.x, qh.x - ql.x, xc.x);
                r.y = norm1(eh.y - el.y, qh.y - ql.y, xc.y);
                r.z = norm1(eh.z - el.z, qh.z - ql.z, xc.z);
                r.w = norm1(eh.w - el.w, qh.w - ql.w, xc.w);
                *reinterpret_cast<float4*>(op + i * Ww + c0) = r;
            }
        }
    }
}

extern "C" void kernel_launch(void* const* d_in, const int* in_sizes, int n_in,
                              void* d_out, int out_size) {
    const float* x = (const float*)d_in[0];
    float* out = (float*)d_out;
    (void)in_sizes; (void)n_in; (void)out_size;

    cudaFuncSetAttribute(localnorm_kernel,
                         cudaFuncAttributeMaxDynamicSharedMemorySize, SMEM_BYTES);
    dim3 grid(Hh / RSEG, NIMG);   // (4, 96)
    localnorm_kernel<<<grid, NT, SMEM_BYTES>>>(x, out);
}

// round 2
// speedup vs baseline: 1.2788x; 1.2788x over previous
#include <cuda_runtime.h>

// LocalNorm2d: 32x32 box-filter local normalization, reflect padding.
// x: (32,3,512,512) fp32 -> out same shape.
//
// Fused, ring-free version:
//   - block = one (n,c) image x one 64-row segment, full 544-wide padded row
//   - 136 active threads own 4 padded columns; running vertical column sums
//     in registers; the row subtracted 32 phases later and the center value
//     are RE-READ from global (L2 hits) instead of a 70KB smem ring
//   - horizontal 32-window via difference of exclusive prefix; the scan writes
//     warp-LOCAL prefixes + warp totals, consumer adds the cross-warp offset
//     itself -> exactly ONE __syncthreads per output row (double-buffered smem)

namespace {
constexpr int Hh   = 512;
constexpr int Ww   = 512;
constexpr int KSZ  = 32;
constexpr int PDv  = 16;
constexpr int PADW = 544;   // Ww + 2*PDv
constexpr int NT   = 160;   // 5 warps
constexpr int NACT = 136;   // PADW/4 column-owning threads
constexpr int RSEG = 64;    // output rows per block
constexpr int NIMG = 32 * 3;
}

__device__ __forceinline__ int rmap(int q) {
    q = q < 0 ? -q : q;
    return q > (Ww - 1) ? 2 * (Ww - 1) - q : q;
}

__device__ __forceinline__ float norm1(float wsum, float wsq, float xc) {
    const float inv = 1.0f / 1024.0f;   // 1/(KS*KS)
    float mean = wsum * inv;
    float msq  = wsq * inv;
    float var  = fabsf(fmaf(-mean, mean, msq));
    float rs   = __frsqrt_rn(fmaxf(var, 1e-24f));
    float stdv = var * rs;              // sqrt(var)
    float v    = __fdividef(xc - mean, stdv + 1e-10f);
    return fminf(6.0f, fmaxf(-6.0f, v));
}

__global__ __launch_bounds__(NT, 6)
void localnorm_kernel(const float* __restrict__ x, float* __restrict__ out)
{
    __shared__ float4 Es[2][NACT];   // warp-local exclusive prefixes (sum)
    __shared__ float4 Eq[2][NACT];   // warp-local exclusive prefixes (sumsq)
    __shared__ float  Ts[2][8];      // warp totals (sum)
    __shared__ float  Tq[2][8];      // warp totals (sumsq)

    const int t      = threadIdx.x;
    const int lane   = t & 31;
    const int wrp    = t >> 5;
    const int img    = blockIdx.y;
    const int rstart = blockIdx.x * RSEG;
    const float* __restrict__ xin = x + (size_t)img * (Hh * Ww);
    float* __restrict__ op        = out + (size_t)img * (Hh * Ww);

    const int  c0       = 4 * t;                 // padded column base
    const bool active   = (t < NACT);
    const bool interior = (t >= 4 && t <= 131);  // 4 cols map contiguously
    int cm0 = 0, cm1 = 0, cm2 = 0, cm3 = 0;
    if (active) {
        cm0 = rmap(c0 + 0 - PDv);
        cm1 = rmap(c0 + 1 - PDv);
        cm2 = rmap(c0 + 2 - PDv);
        cm3 = rmap(c0 + 3 - PDv);
    }

    float s0 = 0.f, s1 = 0.f, s2 = 0.f, s3 = 0.f;   // column sums
    float q0 = 0.f, q1 = 0.f, q2 = 0.f, q3 = 0.f;   // column sums of squares

    #pragma unroll 1
    for (int p = rstart; p < rstart + RSEG + KSZ - 1; ++p) {
        if (active) {
            // add new padded row p
            const float* rowp = xin + rmap(p - PDv) * Ww;
            float4 xn;
            if (interior) {
                xn = *reinterpret_cast<const float4*>(rowp + (c0 - PDv));
            } else {
                xn.x = rowp[cm0]; xn.y = rowp[cm1];
                xn.z = rowp[cm2]; xn.w = rowp[cm3];
            }
            s0 += xn.x; s1 += xn.y; s2 += xn.z; s3 += xn.w;
            q0 = fmaf(xn.x, xn.x, q0); q1 = fmaf(xn.y, xn.y, q1);
            q2 = fmaf(xn.z, xn.z, q2); q3 = fmaf(xn.w, xn.w, q3);

            // subtract padded row p-32 (re-read: L2 hit)
            if (p >= rstart + KSZ) {
                const float* rowo = xin + rmap(p - KSZ - PDv) * Ww;
                float4 xo;
                if (interior) {
                    xo = *reinterpret_cast<const float4*>(rowo + (c0 - PDv));
                } else {
                    xo.x = rowo[cm0]; xo.y = rowo[cm1];
                    xo.z = rowo[cm2]; xo.w = rowo[cm3];
                }
                s0 -= xo.x; s1 -= xo.y; s2 -= xo.z; s3 -= xo.w;
                q0 = fmaf(-xo.x, xo.x, q0); q1 = fmaf(-xo.y, xo.y, q1);
                q2 = fmaf(-xo.z, xo.z, q2); q3 = fmaf(-xo.w, xo.w, q3);
            }
        }

        if (p >= rstart + KSZ - 1) {          // uniform condition
            const int buf = p & 1;

            // thread-local inclusive prefixes over own 4 columns
            float i1 = s0 + s1, i2 = i1 + s2, i3 = i2 + s3;
            float j1 = q0 + q1, j2 = j1 + q2, j3 = j2 + q3;

            // warp-inclusive scan of thread totals (inactive lanes carry 0)
            float ts = i3, tq = j3;
            #pragma unroll
            for (int off = 1; off < 32; off <<= 1) {
                float us = __shfl_up_sync(0xFFFFFFFFu, ts, off);
                float uq = __shfl_up_sync(0xFFFFFFFFu, tq, off);
                if (lane >= off) { ts += us; tq += uq; }
            }
            // warp-LOCAL exclusive prefix at element granularity
            const float bs = ts - i3;
            const float bq = tq - j3;
            float4 es = make_float4(bs, bs + s0, bs + i1, bs + i2);
            float4 eq = make_float4(bq, bq + q0, bq + j1, bq + j2);
            if (active) {
                Es[buf][t] = es;
                Eq[buf][t] = eq;
            }
            if (lane == 31 && wrp < 4) { Ts[buf][wrp] = ts; Tq[buf][wrp] = tq; }
            __syncthreads();   // single barrier; double buffer handles WAR

            if (t < 128) {
                const int i = p - (KSZ - 1);   // output row
                float4 eh = Es[buf][t + 8];
                float4 qh = Eq[buf][t + 8];
                // cross-warp offset: t+8 is in the next warp iff lane >= 24
                float dS = 0.f, dQ = 0.f;
                if (lane >= 24) { dS = Ts[buf][wrp]; dQ = Tq[buf][wrp]; }
                // center x(i, 4t..4t+3): direct global read (L2 hit)
                float4 xc = *reinterpret_cast<const float4*>(xin + i * Ww + c0);
                float4 r;
                r.x = norm1(eh.x - es.x + dS, qh.x - eq.x + dQ, xc.x);
                r.y = norm1(eh.y - es.y + dS, qh.y - eq.y + dQ, xc.y);
                r.z = norm1(eh.z - es.z + dS, qh.z - eq.z + dQ, xc.z);
                r.w = norm1(eh.w - es.w + dS, qh.w - eq.w + dQ, xc.w);
                *reinterpret_cast<float4*>(op + i * Ww + c0) = r;
            }
        }
    }
}

extern "C" void kernel_launch(void* const* d_in, const int* in_sizes, int n_in,
                              void* d_out, int out_size) {
    const float* x = (const float*)d_in[0];
    float* out = (float*)d_out;
    (void)in_sizes; (void)n_in; (void)out_size;

    dim3 grid(Hh / RSEG, NIMG);   // (8, 96) = 768 blocks
    localnorm_kernel<<<grid, NT>>>(x, out);
}

// round 3
// speedup vs baseline: 1.8301x; 1.4311x over previous
#include <cuda_runtime.h>

// LocalNorm2d: 32x32 box-filter local normalization, reflect padding.
// x: (32,3,512,512) fp32 -> out same shape.
//
// Warp-independent fused version (NO barriers, NO shared memory):
//   - each warp owns 128 padded columns (4/thread) -> 96 output columns,
//     and a 64-row output segment of one (n,c) image
//   - vertical 32-row window: running column sums in registers; the row
//     subtracted 32 phases later is re-read from global (L1/L2 hit)
//   - horizontal 32-col window = 8 thread-segments: 3-step shfl_down
//     segment-sum of thread totals + shfl_down(.,8) of thread partials.
//     Everything stays inside one warp -> warps never synchronize.

namespace {
constexpr int Hh   = 512;
constexpr int Ww   = 512;
constexpr int KSZ  = 32;
constexpr int PD   = 16;
constexpr int RSEG = 64;    // output rows per warp
constexpr int NSEG = Hh / RSEG;   // 8
constexpr int WOUT = 96;    // output cols per warp
constexpr int NCG  = 6;     // col groups: 5*96 + 32 = 512
constexpr int NWPB = 8;     // warps per block
constexpr int NT   = NWPB * 32;
constexpr int NIMG = 32 * 3;
}

__device__ __forceinline__ int rmap(int q) {   // reflect into [0, 511]
    q = q < 0 ? -q : q;
    return q > (Ww - 1) ? 2 * (Ww - 1) - q : q;
}

__device__ __forceinline__ float norm1(float wsum, float wsq, float xc) {
    const float inv = 1.0f / 1024.0f;
    float mean = wsum * inv;
    float msq  = wsq * inv;
    float var  = fabsf(fmaf(-mean, mean, msq));
    float rs   = __frsqrt_rn(fmaxf(var, 1e-24f));
    float v    = (xc - mean) * rs;            // eps(1e-10) negligible vs tol
    return fminf(6.0f, fmaxf(-6.0f, v));
}

__global__ __launch_bounds__(NT, 4)
void localnorm_kernel(const float* __restrict__ x, float* __restrict__ out)
{
    const int lane = threadIdx.x & 31;
    const int wrp  = threadIdx.x >> 5;
    const int g    = blockIdx.x * NWPB + wrp;    // 0..47
    const int seg  = g / NCG;                    // 0..7
    const int cg   = g - seg * NCG;              // 0..5
    const int img  = blockIdx.y;

    const float* __restrict__ xin = x   + (size_t)img * (Hh * Ww);
    float*       __restrict__ op  = out + (size_t)img * (Hh * Ww);

    const int wb = cg * WOUT;            // padded-col / output-col base of warp
    const int c0 = wb + 4 * lane;        // this thread's padded col base
    const bool interior = (c0 >= PD && c0 <= Ww + PD - 4);
    const int cm0 = rmap(c0 + 0 - PD);
    const int cm1 = rmap(c0 + 1 - PD);
    const int cm2 = rmap(c0 + 2 - PD);
    const int cm3 = rmap(c0 + 3 - PD);
    const int rstart = seg * RSEG;
    const bool emit  = (lane < 24) && (c0 < Ww);

    float s0 = 0.f, s1 = 0.f, s2 = 0.f, s3 = 0.f;
    float q0 = 0.f, q1 = 0.f, q2 = 0.f, q3 = 0.f;

    auto loadrow = [&](int p) -> float4 {
        int rq = p - PD;
        rq = rq < 0 ? -rq : rq;
        rq = rq > (Hh - 1) ? 2 * (Hh - 1) - rq : rq;
        const float* r = xin + rq * Ww;
        if (interior) {
            return *reinterpret_cast<const float4*>(r + (c0 - PD));
        } else {
            return make_float4(r[cm0], r[cm1], r[cm2], r[cm3]);
        }
    };

    // prologue: accumulate padded rows [rstart, rstart+32)
    #pragma unroll 1
    for (int p = rstart; p < rstart + KSZ; ++p) {
        float4 v = loadrow(p);
        s0 += v.x; s1 += v.y; s2 += v.z; s3 += v.w;
        q0 = fmaf(v.x, v.x, q0); q1 = fmaf(v.y, v.y, q1);
        q2 = fmaf(v.z, v.z, q2); q3 = fmaf(v.w, v.w, q3);
    }

    #pragma unroll 1
    for (int i = rstart; i < rstart + RSEG; ++i) {
        // prefetch next add/sub rows + center (loads issue before compute)
        float4 xn = loadrow(i + KSZ);
        float4 xo = loadrow(i);
        float4 xc;
        if (emit) xc = *reinterpret_cast<const float4*>(xin + i * Ww + c0);

        // thread-local partial prefixes over own 4 cols
        float i1 = s0 + s1, i2 = i1 + s2, i3 = i2 + s3;
        float j1 = q0 + q1, j2 = j1 + q2, j3 = j2 + q3;

        // segment-sum of 8 consecutive thread totals (lanes t..t+7)
        float as = i3 + __shfl_down_sync(0xFFFFFFFFu, i3, 1);
        float aq = j3 + __shfl_down_sync(0xFFFFFFFFu, j3, 1);
        as += __shfl_down_sync(0xFFFFFFFFu, as, 2);
        aq += __shfl_down_sync(0xFFFFFFFFu, aq, 2);
        float T8s = as + __shfl_down_sync(0xFFFFFFFFu, as, 4);
        float T8q = aq + __shfl_down_sync(0xFFFFFFFFu, aq, 4);

        // partials of thread t+8
        float b1s = __shfl_down_sync(0xFFFFFFFFu, s0, 8);
        float b2s = __shfl_down_sync(0xFFFFFFFFu, i1, 8);
        float b3s = __shfl_down_sync(0xFFFFFFFFu, i2, 8);
        float b1q = __shfl_down_sync(0xFFFFFFFFu, q0, 8);
        float b2q = __shfl_down_sync(0xFFFFFFFFu, j1, 8);
        float b3q = __shfl_down_sync(0xFFFFFFFFu, j2, 8);

        if (emit) {
            float w0s = T8s;
            float w1s = T8s - s0 + b1s;
            float w2s = T8s - i1 + b2s;
            float w3s = T8s - i2 + b3s;
            float w0q = T8q;
            float w1q = T8q - q0 + b1q;
            float w2q = T8q - j1 + b2q;
            float w3q = T8q - j2 + b3q;
            float4 r;
            r.x = norm1(w0s, w0q, xc.x);
            r.y = norm1(w1s, w1q, xc.y);
            r.z = norm1(w2s, w2q, xc.z);
            r.w = norm1(w3s, w3q, xc.w);
            *reinterpret_cast<float4*>(op + i * Ww + c0) = r;
        }

        // slide vertical window: add row i+32, drop row i
        s0 += xn.x - xo.x; s1 += xn.y - xo.y;
        s2 += xn.z - xo.z; s3 += xn.w - xo.w;
        q0 = fmaf(xn.x, xn.x, q0); q0 = fmaf(-xo.x, xo.x, q0);
        q1 = fmaf(xn.y, xn.y, q1); q1 = fmaf(-xo.y, xo.y, q1);
        q2 = fmaf(xn.z, xn.z, q2); q2 = fmaf(-xo.z, xo.z, q2);
        q3 = fmaf(xn.w, xn.w, q3); q3 = fmaf(-xo.w, xo.w, q3);
    }
}

extern "C" void kernel_launch(void* const* d_in, const int* in_sizes, int n_in,
                              void* d_out, int out_size) {
    const float* x = (const float*)d_in[0];
    float* out = (float*)d_out;
    (void)in_sizes; (void)n_in; (void)out_size;

    dim3 grid(NSEG * NCG / NWPB, NIMG);   // (6, 96) = 576 blocks, 4608 warps
    localnorm_kernel<<<grid, NT>>>(x, out);
}

// round 4
// speedup vs baseline: 1.9410x; 1.0606x over previous
#include <cuda_runtime.h>

// LocalNorm2d: 32x32 box-filter local normalization, reflect padding.
// x: (32,3,512,512) fp32 -> out same shape.
//
// Warp-independent fused version (no barriers, no smem), streaming-pointer
// edition: each warp owns 128 padded cols (4/thread) x 64 output rows.
// Vertical 32-window via running register column sums (old row re-read from
// L1/L2). Horizontal 32-window via in-warp shfl segment sums. All row
// addressing is pointer += stride; reflection = stride sign flip at one
// known iteration per segment.

namespace {
constexpr int Hh   = 512;
constexpr int Ww   = 512;
constexpr int KSZ  = 32;
constexpr int PD   = 16;
constexpr int RSEG = 64;          // output rows per warp
constexpr int NSEG = Hh / RSEG;   // 8
constexpr int WOUT = 96;          // output cols per warp
constexpr int NCG  = 6;           // col groups per row band
constexpr int NWPB = 8;           // warps per block
constexpr int NT   = NWPB * 32;
constexpr int NIMG = 32 * 3;
}

__device__ __forceinline__ int rmap(int q) {   // reflect into [0, 511]
    q = q < 0 ? -q : q;
    return q > (Ww - 1) ? 2 * (Ww - 1) - q : q;
}

// v = (x - mean)/std computed on raw sums:
//   (1024*x - S) * rsqrt(|1024*Q - S^2|)
__device__ __forceinline__ float norm1(float ws, float wq, float xc) {
    float V  = fabsf(fmaf(-ws, ws, 1024.0f * wq));
    float rs = __frsqrt_rn(fmaxf(V, 1e-12f));
    float v  = fmaf(1024.0f, xc, -ws) * rs;
    return fminf(6.0f, fmaxf(-6.0f, v));
}

__global__ __launch_bounds__(NT, 4)
void localnorm_kernel(const float* __restrict__ x, float* __restrict__ out)
{
    const int lane = threadIdx.x & 31;
    const int wrp  = threadIdx.x >> 5;
    const int g    = blockIdx.x * NWPB + wrp;    // 0..47
    const int seg  = g / NCG;                    // 0..7
    const int cg   = g - seg * NCG;              // 0..5
    const int img  = blockIdx.y;

    const float* __restrict__ xin = x   + (size_t)img * (Hh * Ww);
    float*       __restrict__ op  = out + (size_t)img * (Hh * Ww);

    const int  c0       = cg * WOUT + 4 * lane;      // padded col base
    const bool interior = (c0 >= PD && c0 <= Ww + PD - 4);
    const int  off      = interior ? (c0 - PD) : 0;
    int cm0 = 0, cm1 = 0, cm2 = 0, cm3 = 0;
    if (!interior) {
        cm0 = rmap(c0 + 0 - PD); cm1 = rmap(c0 + 1 - PD);
        cm2 = rmap(c0 + 2 - PD); cm3 = rmap(c0 + 3 - PD);
    }
    const int  rstart = seg * RSEG;
    const bool emit   = (lane < 24) && (c0 < Ww);

    float s0 = 0.f, s1 = 0.f, s2 = 0.f, s3 = 0.f;
    float q0 = 0.f, q1 = 0.f, q2 = 0.f, q3 = 0.f;

    // ---- prologue: accumulate padded rows [rstart, rstart+32) ----
    #pragma unroll 1
    for (int p = rstart; p < rstart + KSZ; ++p) {
        const float* r = xin + rmap(p - PD) * Ww;
        float4 v = interior ? *reinterpret_cast<const float4*>(r + off)
                            : make_float4(r[cm0], r[cm1], r[cm2], r[cm3]);
        s0 += v.x; s1 += v.y; s2 += v.z; s3 += v.w;
        q0 = fmaf(v.x, v.x, q0); q1 = fmaf(v.y, v.y, q1);
        q2 = fmaf(v.z, v.z, q2); q3 = fmaf(v.w, v.w, q3);
    }

    // ---- streaming pointers (row addressing = one add per iteration) ----
    // incoming row: rmap(i+16); linear except seg 7, flips at i == 495
    // outgoing row: rmap(i-16); linear except seg 0, flips at i == 16
    const float* pn = xin + (size_t)(rstart + PD) * Ww + off;
    const float* po = xin + (size_t)rmap(rstart - PD) * Ww + off;
    const float* pc = xin + (size_t)rstart * Ww + c0;
    float*       pw = op  + (size_t)rstart * Ww + c0;
    int dn = Ww;
    int dd = (rstart == 0) ? -Ww : Ww;
    const int flip_o = (rstart == 0) ? PD : 0x7fffffff;            // 16
    const int flip_n = (rstart + RSEG == Hh) ? (Hh - PD - 1)        // 495
                                             : 0x7fffffff;

    #pragma unroll 2
    for (int i = rstart; i < rstart + RSEG; ++i) {
        float4 xn = interior ? *reinterpret_cast<const float4*>(pn)
                             : make_float4(pn[cm0], pn[cm1], pn[cm2], pn[cm3]);
        float4 xo = interior ? *reinterpret_cast<const float4*>(po)
                             : make_float4(po[cm0], po[cm1], po[cm2], po[cm3]);
        if (i == flip_n) dn = -Ww;
        if (i == flip_o) dd =  Ww;
        pn += dn; po += dd;
        float4 xc;
        if (emit) xc = *reinterpret_cast<const float4*>(pc);
        pc += Ww;

        // thread-local partial prefixes over own 4 cols
        float i1 = s0 + s1, i2 = i1 + s2, i3 = i2 + s3;
        float j1 = q0 + q1, j2 = j1 + q2, j3 = j2 + q3;

        // segment sum of 8 consecutive thread totals (lanes t..t+7)
        float as = i3 + __shfl_down_sync(0xFFFFFFFFu, i3, 1);
        float aq = j3 + __shfl_down_sync(0xFFFFFFFFu, j3, 1);
        as += __shfl_down_sync(0xFFFFFFFFu, as, 2);
        aq += __shfl_down_sync(0xFFFFFFFFu, aq, 2);
        float T8s = as + __shfl_down_sync(0xFFFFFFFFu, as, 4);
        float T8q = aq + __shfl_down_sync(0xFFFFFFFFu, aq, 4);

        // partial prefixes of thread t+8
        float b1s = __shfl_down_sync(0xFFFFFFFFu, s0, 8);
        float b2s = __shfl_down_sync(0xFFFFFFFFu, i1, 8);
        float b3s = __shfl_down_sync(0xFFFFFFFFu, i2, 8);
        float b1q = __shfl_down_sync(0xFFFFFFFFu, q0, 8);
        float b2q = __shfl_down_sync(0xFFFFFFFFu, j1, 8);
        float b3q = __shfl_down_sync(0xFFFFFFFFu, j2, 8);

        if (emit) {
            float4 r;
            r.x = norm1(T8s,             T8q,             xc.x);
            r.y = norm1(T8s - s0 + b1s,  T8q - q0 + b1q,  xc.y);
            r.z = norm1(T8s - i1 + b2s,  T8q - j1 + b2q,  xc.z);
            r.w = norm1(T8s - i2 + b3s,  T8q - j2 + b3q,  xc.w);
            *reinterpret_cast<float4*>(pw) = r;
        }
        pw += Ww;

        // slide vertical window
        s0 += xn.x - xo.x; s1 += xn.y - xo.y;
        s2 += xn.z - xo.z; s3 += xn.w - xo.w;
        q0 = fmaf(xn.x, xn.x, q0); q0 = fmaf(-xo.x, xo.x, q0);
        q1 = fmaf(xn.y, xn.y, q1); q1 = fmaf(-xo.y, xo.y, q1);
        q2 = fmaf(xn.z, xn.z, q2); q2 = fmaf(-xo.z, xo.z, q2);
        q3 = fmaf(xn.w, xn.w, q3); q3 = fmaf(-xo.w, xo.w, q3);
    }
}

extern "C" void kernel_launch(void* const* d_in, const int* in_sizes, int n_in,
                              void* d_out, int out_size) {
    const float* x = (const float*)d_in[0];
    float* out = (float*)d_out;
    (void)in_sizes; (void)n_in; (void)out_size;

    dim3 grid(NSEG * NCG / NWPB, NIMG);   // (6, 96) = 576 blocks, 4608 warps
    localnorm_kernel<<<grid, NT>>>(x, out);
}